// round 3
// baseline (speedup 1.0000x reference)
#include <cuda_runtime.h>
#include <math.h>

// ---------------- problem constants ----------------
#define NN 50000      // nodes
#define NE 200000     // edges
#define DIN 768
#define DHID 256
#define DOUT 64
#define NH 4          // heads layer1
#define NEG 0.2f
#define LNEPS 1e-5f

// ---------------- scratch (device globals; no allocation allowed) ----------
__device__ float g_h1[(size_t)NN * DHID];     // layer1 projection, later reused for post-LN activations
__device__ float g_agg1[(size_t)NN * DHID];   // layer1 aggregated output
__device__ float g_h2[(size_t)NN * DOUT];     // layer2 projection
__device__ float g_agg2[(size_t)NN * DOUT];   // layer2 aggregated output
__device__ float g_als1[NN * NH];
__device__ float g_ald1[NN * NH];
__device__ float g_den1[NN * NH];
__device__ float g_als2[NN];
__device__ float g_ald2[NN];
__device__ float g_den2[NN];
__device__ float g_exp1[(size_t)NE * NH];
__device__ float g_exp2[NE];
__device__ int   g_rel[NN];                   // winner edge id, then relation id (-1 = untouched)

// ---------------- f32x2 packed-FMA helpers (Blackwell dual-rate fp32) ------
__device__ __forceinline__ unsigned long long f2pack(float x, float y) {
    unsigned long long r;
    asm("mov.b64 %0, {%1, %2};" : "=l"(r) : "r"(__float_as_uint(x)), "r"(__float_as_uint(y)));
    return r;
}
__device__ __forceinline__ void f2unpack(unsigned long long v, float& x, float& y) {
    unsigned int a, b;
    asm("mov.b64 {%0, %1}, %2;" : "=r"(a), "=r"(b) : "l"(v));
    x = __uint_as_float(a); y = __uint_as_float(b);
}
#define FMA_F32X2(d, a, b) asm("fma.rn.f32x2 %0, %1, %2, %0;" : "+l"(d) : "l"(a), "l"(b))

// ---------------- init: zero accumulators, winner = -1 ---------------------
__global__ void k_init() {
    int i = blockIdx.x * blockDim.x + threadIdx.x;
    int stride = gridDim.x * blockDim.x;
    for (int j = i; j < NN * DHID; j += stride) g_agg1[j] = 0.f;
    for (int j = i; j < NN * DOUT; j += stride) g_agg2[j] = 0.f;
    for (int j = i; j < NN * NH;   j += stride) g_den1[j] = 0.f;
    for (int j = i; j < NN;        j += stride) { g_den2[j] = 0.f; g_rel[j] = -1; }
}

// winner[src[e]] = max edge id  (deterministic "last write wins")
__global__ void k_winner(const int* __restrict__ src) {
    int e = blockIdx.x * blockDim.x + threadIdx.x;
    if (e < NE) atomicMax(&g_rel[src[e]], e);
}
__global__ void k_rel(const int* __restrict__ etype) {
    int n = blockIdx.x * blockDim.x + threadIdx.x;
    if (n < NN) { int w = g_rel[n]; g_rel[n] = (w < 0) ? -1 : etype[w]; }
}

// ---------------- tiled SGEMM with packed f32x2 FMA ------------------------
// C[M,Ncols] = A'[M,K] * B[K,Ncols];  A'[n,k] = A[n,k] (+ emb[rel[n],k] if FUSE)
template<int BM, int BN, int BK, int TM, int TN, bool FUSE>
__global__ void k_gemm(const float* __restrict__ A, const float* __restrict__ B,
                       float* __restrict__ C, int M, int Ncols, int K,
                       const float* __restrict__ emb) {
    constexpr int NT = (BM / TM) * (BN / TN);
    __shared__ float As[2][BK][BM];
    __shared__ float Bs[2][BK][BN];
    const int tid = threadIdx.x;
    const int tx = tid % (BN / TN);
    const int ty = tid / (BN / TN);
    const int row0 = blockIdx.y * BM;
    const int col0 = blockIdx.x * BN;

    auto loadA = [&](int buf, int kk) {
#pragma unroll
        for (int i = 0; i < (BM * BK) / (4 * NT); i++) {
            int idx = (tid + i * NT) * 4;
            int r = idx / BK;
            int kq = idx % BK;
            int grow = row0 + r;
            float4 v = make_float4(0.f, 0.f, 0.f, 0.f);
            if (grow < M) {
                v = *reinterpret_cast<const float4*>(&A[(size_t)grow * K + kk + kq]);
                if (FUSE) {
                    int rl = __ldg(&g_rel[grow]);
                    if (rl >= 0) {
                        float4 e4 = *reinterpret_cast<const float4*>(&emb[(size_t)rl * K + kk + kq]);
                        v.x += e4.x; v.y += e4.y; v.z += e4.z; v.w += e4.w;
                    }
                }
            }
            As[buf][kq + 0][r] = v.x;
            As[buf][kq + 1][r] = v.y;
            As[buf][kq + 2][r] = v.z;
            As[buf][kq + 3][r] = v.w;
        }
    };
    auto loadB = [&](int buf, int kk) {
#pragma unroll
        for (int i = 0; i < (BK * BN) / (4 * NT); i++) {
            int idx = (tid + i * NT) * 4;
            int kr = idx / BN;
            int c = idx % BN;
            *reinterpret_cast<float4*>(&Bs[buf][kr][c]) =
                *reinterpret_cast<const float4*>(&B[(size_t)(kk + kr) * Ncols + col0 + c]);
        }
    };

    unsigned long long acc[TM][TN / 2];
#pragma unroll
    for (int m = 0; m < TM; m++)
#pragma unroll
        for (int n = 0; n < TN / 2; n++) acc[m][n] = 0ull;

    loadA(0, 0); loadB(0, 0);
    __syncthreads();
    const int KT = K / BK;
    for (int kt = 0; kt < KT; kt++) {
        int cur = kt & 1;
        if (kt + 1 < KT) { loadA(cur ^ 1, (kt + 1) * BK); loadB(cur ^ 1, (kt + 1) * BK); }
#pragma unroll
        for (int kk = 0; kk < BK; kk++) {
            unsigned long long a2[TM], b2[TN / 2];
#pragma unroll
            for (int m = 0; m < TM; m++) {
                float a = As[cur][kk][ty * TM + m];
                a2[m] = f2pack(a, a);
            }
#pragma unroll
            for (int n = 0; n < TN / 2; n++) {
                float2 bv = *reinterpret_cast<const float2*>(&Bs[cur][kk][tx * TN + 2 * n]);
                b2[n] = f2pack(bv.x, bv.y);
            }
#pragma unroll
            for (int m = 0; m < TM; m++)
#pragma unroll
                for (int n = 0; n < TN / 2; n++)
                    FMA_F32X2(acc[m][n], a2[m], b2[n]);
        }
        __syncthreads();
    }
#pragma unroll
    for (int m = 0; m < TM; m++) {
        int grow = row0 + ty * TM + m;
        if (grow < M) {
#pragma unroll
            for (int n = 0; n < TN / 2; n++) {
                float x, y; f2unpack(acc[m][n], x, y);
                *reinterpret_cast<float2*>(&C[(size_t)grow * Ncols + col0 + tx * TN + 2 * n]) =
                    make_float2(x, y);
            }
        }
    }
}

// ---------------- layer1 attention logits: warp per node -------------------
__global__ void k_logits1(const float* __restrict__ asrc, const float* __restrict__ adst) {
    int w = (blockIdx.x * blockDim.x + threadIdx.x) >> 5;
    int lane = threadIdx.x & 31;
    if (w >= NN) return;
    const float4* hp = reinterpret_cast<const float4*>(&g_h1[(size_t)w * DHID + lane * 8]);
    float4 v0 = hp[0], v1 = hp[1];
    const float4* sp = reinterpret_cast<const float4*>(&asrc[lane * 8]);
    const float4* dp = reinterpret_cast<const float4*>(&adst[lane * 8]);
    float4 s0 = sp[0], s1 = sp[1], d0 = dp[0], d1 = dp[1];
    float ss = v0.x * s0.x + v0.y * s0.y + v0.z * s0.z + v0.w * s0.w
             + v1.x * s1.x + v1.y * s1.y + v1.z * s1.z + v1.w * s1.w;
    float sd = v0.x * d0.x + v0.y * d0.y + v0.z * d0.z + v0.w * d0.w
             + v1.x * d1.x + v1.y * d1.y + v1.z * d1.z + v1.w * d1.w;
#pragma unroll
    for (int off = 4; off > 0; off >>= 1) {
        ss += __shfl_xor_sync(0xffffffffu, ss, off);
        sd += __shfl_xor_sync(0xffffffffu, sd, off);
    }
    if ((lane & 7) == 0) {
        int head = lane >> 3;
        g_als1[w * NH + head] = ss;
        g_ald1[w * NH + head] = sd;
    }
}

// ---------------- layer1 edge exp + denominator ----------------------------
__global__ void k_exp1(const int* __restrict__ src, const int* __restrict__ dst) {
    int e = blockIdx.x * blockDim.x + threadIdx.x;
    if (e >= NE) return;
    int s = src[e], d = dst[e];
#pragma unroll
    for (int h = 0; h < NH; h++) {
        float v = g_als1[s * NH + h] + g_ald1[d * NH + h];
        v = v > 0.f ? v : NEG * v;
        float ex = expf(v);
        g_exp1[(size_t)e * NH + h] = ex;
        atomicAdd(&g_den1[d * NH + h], ex);
    }
}
__global__ void k_invden1() {
    int i = blockIdx.x * blockDim.x + threadIdx.x;
    if (i < NN * NH) g_den1[i] = 1.f / g_den1[i];
}

// ---------------- layer1 aggregation: 64 threads/edge, float4 atomics ------
__global__ void k_agg1(const int* __restrict__ src, const int* __restrict__ dst) {
    int t = blockIdx.x * blockDim.x + threadIdx.x;
    int e = t >> 6;
    int sub = t & 63;
    if (e >= NE) return;
    int s = src[e], d = dst[e];
    int head = sub >> 4;
    float alpha = g_exp1[(size_t)e * NH + head] * g_den1[d * NH + head];
    float4 v = *reinterpret_cast<const float4*>(&g_h1[(size_t)s * DHID + sub * 4]);
    v.x *= alpha; v.y *= alpha; v.z *= alpha; v.w *= alpha;
    atomicAdd(reinterpret_cast<float4*>(&g_agg1[(size_t)d * DHID + sub * 4]), v);
}

// ---------------- LayerNorm(256) + ELU, warp per node, writes into g_h1 ----
__global__ void k_ln1(const float* __restrict__ bias, const float* __restrict__ g,
                      const float* __restrict__ be) {
    int w = (blockIdx.x * blockDim.x + threadIdx.x) >> 5;
    int lane = threadIdx.x & 31;
    if (w >= NN) return;
    const float4* p = reinterpret_cast<const float4*>(&g_agg1[(size_t)w * DHID + lane * 8]);
    const float4* bp = reinterpret_cast<const float4*>(&bias[lane * 8]);
    float4 v0 = p[0], v1 = p[1];
    float4 b0 = bp[0], b1v = bp[1];
    v0.x += b0.x; v0.y += b0.y; v0.z += b0.z; v0.w += b0.w;
    v1.x += b1v.x; v1.y += b1v.y; v1.z += b1v.z; v1.w += b1v.w;
    float s  = v0.x + v0.y + v0.z + v0.w + v1.x + v1.y + v1.z + v1.w;
    float sq = v0.x * v0.x + v0.y * v0.y + v0.z * v0.z + v0.w * v0.w
             + v1.x * v1.x + v1.y * v1.y + v1.z * v1.z + v1.w * v1.w;
#pragma unroll
    for (int off = 16; off > 0; off >>= 1) {
        s  += __shfl_xor_sync(0xffffffffu, s, off);
        sq += __shfl_xor_sync(0xffffffffu, sq, off);
    }
    float mu = s * (1.f / DHID);
    float var = sq * (1.f / DHID) - mu * mu;
    float rstd = rsqrtf(var + LNEPS);
    const float4* gp = reinterpret_cast<const float4*>(&g[lane * 8]);
    const float4* ep = reinterpret_cast<const float4*>(&be[lane * 8]);
    float4 g0 = gp[0], g1v = gp[1], e0 = ep[0], e1 = ep[1];
    float out[8];
    float in[8]  = {v0.x, v0.y, v0.z, v0.w, v1.x, v1.y, v1.z, v1.w};
    float gg[8]  = {g0.x, g0.y, g0.z, g0.w, g1v.x, g1v.y, g1v.z, g1v.w};
    float bb[8]  = {e0.x, e0.y, e0.z, e0.w, e1.x, e1.y, e1.z, e1.w};
#pragma unroll
    for (int i = 0; i < 8; i++) {
        float y = (in[i] - mu) * rstd * gg[i] + bb[i];
        out[i] = y > 0.f ? y : expm1f(y);
    }
    float4* op = reinterpret_cast<float4*>(&g_h1[(size_t)w * DHID + lane * 8]);
    op[0] = make_float4(out[0], out[1], out[2], out[3]);
    op[1] = make_float4(out[4], out[5], out[6], out[7]);
}

// ---------------- layer2 attention logits: warp per node -------------------
__global__ void k_logits2(const float* __restrict__ asrc, const float* __restrict__ adst) {
    int w = (blockIdx.x * blockDim.x + threadIdx.x) >> 5;
    int lane = threadIdx.x & 31;
    if (w >= NN) return;
    float2 v = *reinterpret_cast<const float2*>(&g_h2[(size_t)w * DOUT + lane * 2]);
    float2 a = *reinterpret_cast<const float2*>(&asrc[lane * 2]);
    float2 b = *reinterpret_cast<const float2*>(&adst[lane * 2]);
    float ss = v.x * a.x + v.y * a.y;
    float sd = v.x * b.x + v.y * b.y;
#pragma unroll
    for (int off = 16; off > 0; off >>= 1) {
        ss += __shfl_xor_sync(0xffffffffu, ss, off);
        sd += __shfl_xor_sync(0xffffffffu, sd, off);
    }
    if (lane == 0) { g_als2[w] = ss; g_ald2[w] = sd; }
}

__global__ void k_exp2(const int* __restrict__ src, const int* __restrict__ dst) {
    int e = blockIdx.x * blockDim.x + threadIdx.x;
    if (e >= NE) return;
    int s = src[e], d = dst[e];
    float v = g_als2[s] + g_ald2[d];
    v = v > 0.f ? v : NEG * v;
    float ex = expf(v);
    g_exp2[e] = ex;
    atomicAdd(&g_den2[d], ex);
}
__global__ void k_invden2() {
    int i = blockIdx.x * blockDim.x + threadIdx.x;
    if (i < NN) g_den2[i] = 1.f / g_den2[i];
}

// ---------------- layer2 aggregation: 16 threads/edge ----------------------
__global__ void k_agg2(const int* __restrict__ src, const int* __restrict__ dst) {
    int t = blockIdx.x * blockDim.x + threadIdx.x;
    int e = t >> 4;
    int sub = t & 15;
    if (e >= NE) return;
    int s = src[e], d = dst[e];
    float alpha = g_exp2[e] * g_den2[d];
    float4 v = *reinterpret_cast<const float4*>(&g_h2[(size_t)s * DOUT + sub * 4]);
    v.x *= alpha; v.y *= alpha; v.z *= alpha; v.w *= alpha;
    atomicAdd(reinterpret_cast<float4*>(&g_agg2[(size_t)d * DOUT + sub * 4]), v);
}

// ---------------- final LayerNorm(64) -> d_out -----------------------------
__global__ void k_ln2(const float* __restrict__ bias, const float* __restrict__ g,
                      const float* __restrict__ be, float* __restrict__ out) {
    int w = (blockIdx.x * blockDim.x + threadIdx.x) >> 5;
    int lane = threadIdx.x & 31;
    if (w >= NN) return;
    float2 v = *reinterpret_cast<const float2*>(&g_agg2[(size_t)w * DOUT + lane * 2]);
    float2 b = *reinterpret_cast<const float2*>(&bias[lane * 2]);
    v.x += b.x; v.y += b.y;
    float s = v.x + v.y;
    float sq = v.x * v.x + v.y * v.y;
#pragma unroll
    for (int off = 16; off > 0; off >>= 1) {
        s  += __shfl_xor_sync(0xffffffffu, s, off);
        sq += __shfl_xor_sync(0xffffffffu, sq, off);
    }
    float mu = s * (1.f / DOUT);
    float var = sq * (1.f / DOUT) - mu * mu;
    float rstd = rsqrtf(var + LNEPS);
    float2 gg = *reinterpret_cast<const float2*>(&g[lane * 2]);
    float2 bb = *reinterpret_cast<const float2*>(&be[lane * 2]);
    float2 o;
    o.x = (v.x - mu) * rstd * gg.x + bb.x;
    o.y = (v.y - mu) * rstd * gg.y + bb.y;
    *reinterpret_cast<float2*>(&out[(size_t)w * DOUT + lane * 2]) = o;
}

// ---------------- host launch ----------------------------------------------
extern "C" void kernel_launch(void* const* d_in, const int* in_sizes, int n_in,
                              void* d_out, int out_size) {
    const float* x    = (const float*)d_in[0];
    const int*   ei   = (const int*)d_in[1];   // [2, E]: row0 = src, row1 = dst
    const int*   et   = (const int*)d_in[2];
    const float* emb  = (const float*)d_in[3];
    const float* W1   = (const float*)d_in[4];
    const float* as1  = (const float*)d_in[5];
    const float* ad1  = (const float*)d_in[6];
    const float* b1   = (const float*)d_in[7];
    const float* g1   = (const float*)d_in[8];
    const float* be1  = (const float*)d_in[9];
    const float* W2   = (const float*)d_in[10];
    const float* as2  = (const float*)d_in[11];
    const float* ad2  = (const float*)d_in[12];
    const float* b2   = (const float*)d_in[13];
    const float* g2   = (const float*)d_in[14];
    const float* be2  = (const float*)d_in[15];
    float* out = (float*)d_out;

    const int* src = ei;
    const int* dst = ei + NE;

    void *p_h1, *p_h2;
    cudaGetSymbolAddress(&p_h1, g_h1);
    cudaGetSymbolAddress(&p_h2, g_h2);

    // 1. init scratch
    k_init<<<2048, 256>>>();
    // 2. last-write-wins relation per src node
    k_winner<<<(NE + 255) / 256, 256>>>(src);
    k_rel<<<(NN + 255) / 256, 256>>>(et);
    // 3. GEMM1: (x + emb[rel]) @ W1 -> g_h1   [50000 x 256]
    {
        dim3 grid(DHID / 128, (NN + 127) / 128);
        k_gemm<128, 128, 16, 8, 8, true><<<grid, 256>>>(
            x, W1, (float*)p_h1, NN, DHID, DIN, emb);
    }
    // 4. attention layer 1
    k_logits1<<<(NN * 32) / 256, 256>>>(as1, ad1);
    k_exp1<<<(NE + 255) / 256, 256>>>(src, dst);
    k_invden1<<<(NN * NH + 255) / 256, 256>>>();
    k_agg1<<<(NE * 64) / 256, 256>>>(src, dst);
    // 5. LN + ELU -> g_h1 (reuse)
    k_ln1<<<(NN * 32) / 256, 256>>>(b1, g1, be1);
    // 6. GEMM2: h @ W2 -> g_h2  [50000 x 64]
    {
        dim3 grid(DOUT / 64, (NN + 127) / 128);
        k_gemm<128, 64, 16, 8, 8, false><<<grid, 128>>>(
            (const float*)p_h1, W2, (float*)p_h2, NN, DOUT, DHID, nullptr);
    }
    // 7. attention layer 2
    k_logits2<<<(NN * 32) / 256, 256>>>(as2, ad2);
    k_exp2<<<(NE + 255) / 256, 256>>>(src, dst);
    k_invden2<<<(NN + 255) / 256, 256>>>();
    k_agg2<<<(NE * 16) / 256, 256>>>(src, dst);
    // 8. final LayerNorm -> d_out
    k_ln2<<<(NN * 32) / 256, 256>>>(b2, g2, be2, out);
}

// round 8
// speedup vs baseline: 1.1312x; 1.1312x over previous
#include <cuda_runtime.h>
#include <cuda_bf16.h>
#include <math.h>
#include <stdint.h>

// ---------------- problem constants ----------------
#define NN 50000      // nodes
#define NE 200000     // edges
#define DIN 768
#define DHID 256
#define DOUT 64
#define NH 4          // heads layer1
#define NEG 0.2f
#define LNEPS 1e-5f

// ---------------- scratch (device globals; no allocation allowed) ----------
__device__ float g_h1[(size_t)NN * DHID];     // layer1 projection, later post-LN activations
__device__ float g_agg1[(size_t)NN * DHID];   // layer1 aggregated output
__device__ float g_h2[(size_t)NN * DOUT];     // layer2 projection
__device__ float g_agg2[(size_t)NN * DOUT];   // layer2 aggregated output
__device__ float g_als1[NN * NH];
__device__ float g_ald1[NN * NH];
__device__ float g_den1[NN * NH];
__device__ float g_als2[NN];
__device__ float g_ald2[NN];
__device__ float g_den2[NN];
__device__ float g_exp1[(size_t)NE * NH];
__device__ float g_exp2[NE];
__device__ int   g_rel[NN];                   // winner edge id, then relation id (-1 = untouched)

// ---------------- helpers ---------------------------------------------------
__device__ __forceinline__ uint32_t s2u(const void* p) {
    uint32_t a;
    asm("{ .reg .u64 t; cvta.to.shared.u64 t, %1; cvt.u32.u64 %0, t; }" : "=r"(a) : "l"(p));
    return a;
}
// split a float pair into bf16-hi pair (packed) and bf16-lo (residual) pair
__device__ __forceinline__ void cvt_split2(float e0, float e1, uint32_t& ph, uint32_t& pl) {
    asm("cvt.rn.bf16x2.f32 %0, %1, %2;" : "=r"(ph) : "f"(e1), "f"(e0));
    float h0 = __uint_as_float(ph << 16);
    float h1 = __uint_as_float(ph & 0xffff0000u);
    float l0 = e0 - h0, l1 = e1 - h1;
    asm("cvt.rn.bf16x2.f32 %0, %1, %2;" : "=r"(pl) : "f"(l1), "f"(l0));
}

#define LDSM4(d, addr) \
    asm volatile("ldmatrix.sync.aligned.m8n8.x4.shared.b16 {%0,%1,%2,%3}, [%4];" \
        : "=r"((d)[0]), "=r"((d)[1]), "=r"((d)[2]), "=r"((d)[3]) : "r"(addr))
#define LDSM4T(d, addr) \
    asm volatile("ldmatrix.sync.aligned.m8n8.x4.trans.shared.b16 {%0,%1,%2,%3}, [%4];" \
        : "=r"((d)[0]), "=r"((d)[1]), "=r"((d)[2]), "=r"((d)[3]) : "r"(addr))
#define MMA_BF16(c, a, b0, b1) \
    asm volatile("mma.sync.aligned.m16n8k16.row.col.f32.bf16.bf16.f32 " \
        "{%0,%1,%2,%3}, {%4,%5,%6,%7}, {%8,%9}, {%0,%1,%2,%3};" \
        : "+f"((c)[0]), "+f"((c)[1]), "+f"((c)[2]), "+f"((c)[3]) \
        : "r"((a)[0]), "r"((a)[1]), "r"((a)[2]), "r"((a)[3]), "r"(b0), "r"(b1))

// ---------------- init: zero accumulators, winner = -1 ---------------------
__global__ void k_init() {
    int i = blockIdx.x * blockDim.x + threadIdx.x;
    int stride = gridDim.x * blockDim.x;
    for (int j = i; j < NN * DHID; j += stride) g_agg1[j] = 0.f;
    for (int j = i; j < NN * DOUT; j += stride) g_agg2[j] = 0.f;
    for (int j = i; j < NN * NH;   j += stride) g_den1[j] = 0.f;
    for (int j = i; j < NN;        j += stride) { g_den2[j] = 0.f; g_rel[j] = -1; }
}

// winner[src[e]] = max edge id  (deterministic "last write wins")
__global__ void k_winner(const int* __restrict__ src) {
    int e = blockIdx.x * blockDim.x + threadIdx.x;
    if (e < NE) atomicMax(&g_rel[src[e]], e);
}
__global__ void k_rel(const int* __restrict__ etype) {
    int n = blockIdx.x * blockDim.x + threadIdx.x;
    if (n < NN) { int w = g_rel[n]; g_rel[n] = (w < 0) ? -1 : etype[w]; }
}

// ---------------- GEMM1 via mma.sync bf16 (2-term split, 3 MMAs) -----------
// g_h1[m,n] = sum_k (x[m,k] + emb[rel[m],k]) * W1[k,n]
// BM=128, BN=128, BK=32. 8 warps: warp tile 64x32 (warp_m 0..1, warp_n 0..3).
// SMEM per buffer: Ah[128][32] pad80B | Al | Bh[32][128] pad272B | Bl
#define A_STRIDE 80
#define B_STRIDE 272
#define A_TILE (128 * A_STRIDE)          // 10240
#define B_TILE (32 * B_STRIDE)           // 8704
#define BUF_BYTES (2 * A_TILE + 2 * B_TILE)  // 37888
#define G1_SMEM (2 * BUF_BYTES)              // 75776

__global__ void __launch_bounds__(256, 1) k_gemm1_mma(const float* __restrict__ x,
                                                      const float* __restrict__ emb,
                                                      const float* __restrict__ W1) {
    extern __shared__ char smem[];
    const uint32_t sb = s2u(smem);
    const int tid = threadIdx.x;
    const int wid = tid >> 5, lane = tid & 31;
    const int warp_m = wid >> 2;          // 0..1
    const int warp_n = wid & 3;           // 0..3
    const int m0 = blockIdx.y * 128;
    const int col0 = blockIdx.x * 128;

    // --- per-thread gmem load setup (fixed across chunks) ---
    const float* xptr[4];
    const float* eptr[4];
    int avalid[4];
    uint32_t a_sts[4], b_sts[4];
    const float* wptr[4];
    {
#pragma unroll
        for (int i = 0; i < 4; i++) {
            int f = tid + i * 256;          // A float4 index: 128 rows x 8 f4
            int r = f >> 3, c4 = f & 7;
            int gm = m0 + r;
            avalid[i] = (gm < NN);
            xptr[i] = avalid[i] ? (x + (size_t)gm * DIN + c4 * 4) : x;
            int rl = avalid[i] ? g_rel[gm] : -1;
            eptr[i] = (rl >= 0) ? (emb + (size_t)rl * DIN + c4 * 4) : nullptr;
            a_sts[i] = (uint32_t)(r * A_STRIDE + c4 * 8);
            int kr = f >> 5, bc4 = f & 31;  // B float4 index: 32 rows x 32 f4
            wptr[i] = W1 + (size_t)kr * 256 + col0 + bc4 * 4;
            b_sts[i] = (uint32_t)(kr * B_STRIDE + bc4 * 8);
        }
    }
    // ldmatrix per-lane address bases (byte offsets within tiles)
    const uint32_t a_lm = (uint32_t)((warp_m * 64 + (lane & 15)) * A_STRIDE + (lane >> 4) * 16);
    const uint32_t b_lm = (uint32_t)(((lane & 7) + ((lane >> 3) & 1) * 8) * B_STRIDE
                                     + (warp_n * 32 + (lane >> 4) * 8) * 2);

    float acc[4][4][4];
#pragma unroll
    for (int mi = 0; mi < 4; mi++)
#pragma unroll
        for (int nf = 0; nf < 4; nf++)
#pragma unroll
            for (int j = 0; j < 4; j++) acc[mi][nf][j] = 0.f;

    float4 pa[4], pb[4];
    auto ldg_chunk = [&](int kt) {
        int k0 = kt * 32;
#pragma unroll
        for (int i = 0; i < 4; i++) {
            float4 v = make_float4(0.f, 0.f, 0.f, 0.f);
            if (avalid[i]) {
                v = *reinterpret_cast<const float4*>(xptr[i] + k0);
                if (eptr[i]) {
                    float4 e = *reinterpret_cast<const float4*>(eptr[i] + k0);
                    v.x += e.x; v.y += e.y; v.z += e.z; v.w += e.w;
                }
            }
            pa[i] = v;
            pb[i] = *reinterpret_cast<const float4*>(wptr[i] + (size_t)k0 * 256);
        }
    };
    auto sts_chunk = [&](int buf) {
        char* base = smem + buf * BUF_BYTES;
#pragma unroll
        for (int i = 0; i < 4; i++) {
            uint32_t h0, l0, h1, l1;
            cvt_split2(pa[i].x, pa[i].y, h0, l0);
            cvt_split2(pa[i].z, pa[i].w, h1, l1);
            *reinterpret_cast<uint2*>(base + a_sts[i]) = make_uint2(h0, h1);
            *reinterpret_cast<uint2*>(base + A_TILE + a_sts[i]) = make_uint2(l0, l1);
            cvt_split2(pb[i].x, pb[i].y, h0, l0);
            cvt_split2(pb[i].z, pb[i].w, h1, l1);
            *reinterpret_cast<uint2*>(base + 2 * A_TILE + b_sts[i]) = make_uint2(h0, h1);
            *reinterpret_cast<uint2*>(base + 2 * A_TILE + B_TILE + b_sts[i]) = make_uint2(l0, l1);
        }
    };

    ldg_chunk(0);
    sts_chunk(0);
    __syncthreads();

    const int NCHUNK = DIN / 32;   // 24
    for (int kt = 0; kt < NCHUNK; kt++) {
        const int buf = kt & 1;
        if (kt + 1 < NCHUNK) ldg_chunk(kt + 1);

        const uint32_t base = sb + (uint32_t)buf * BUF_BYTES;
        const uint32_t sAh = base, sAl = base + A_TILE;
        const uint32_t sBh = base + 2 * A_TILE, sBl = sBh + B_TILE;
#pragma unroll
        for (int s = 0; s < 2; s++) {
            uint32_t bh[2][4], bl[2][4];
            LDSM4T(bh[0], sBh + b_lm + s * (16 * B_STRIDE));
            LDSM4T(bh[1], sBh + b_lm + s * (16 * B_STRIDE) + 32);
            LDSM4T(bl[0], sBl + b_lm + s * (16 * B_STRIDE));
            LDSM4T(bl[1], sBl + b_lm + s * (16 * B_STRIDE) + 32);
#pragma unroll
            for (int mi = 0; mi < 4; mi++) {
                uint32_t ah[4], al[4];
                LDSM4(ah, sAh + a_lm + mi * (16 * A_STRIDE) + s * 32);
                LDSM4(al, sAl + a_lm + mi * (16 * A_STRIDE) + s * 32);
#pragma unroll
                for (int nf = 0; nf < 4; nf++) {
                    uint32_t b0h = bh[nf >> 1][(nf & 1) * 2], b1h = bh[nf >> 1][(nf & 1) * 2 + 1];
                    uint32_t b0l = bl[nf >> 1][(nf & 1) * 2], b1l = bl[nf >> 1][(nf & 1) * 2 + 1];
                    MMA_BF16(acc[mi][nf], ah, b0h, b1h);
                    MMA_BF16(acc[mi][nf], al, b0h, b1h);
                    MMA_BF16(acc[mi][nf], ah, b0l, b1l);
                }
            }
        }
        __syncthreads();
        if (kt + 1 < NCHUNK) {
            sts_chunk(buf ^ 1);
            __syncthreads();
        }
    }

    // epilogue
#pragma unroll
    for (int mi = 0; mi < 4; mi++) {
        int r0 = m0 + warp_m * 64 + mi * 16 + (lane >> 2);
#pragma unroll
        for (int nf = 0; nf < 4; nf++) {
            int c = col0 + warp_n * 32 + nf * 8 + (lane & 3) * 2;
            if (r0 < NN)
                *reinterpret_cast<float2*>(&g_h1[(size_t)r0 * DHID + c]) =
                    make_float2(acc[mi][nf][0], acc[mi][nf][1]);
            if (r0 + 8 < NN)
                *reinterpret_cast<float2*>(&g_h1[(size_t)(r0 + 8) * DHID + c]) =
                    make_float2(acc[mi][nf][2], acc[mi][nf][3]);
        }
    }
}

// ---------------- f32x2 packed-FMA helpers (for GEMM2) ---------------------
__device__ __forceinline__ unsigned long long f2pack(float x, float y) {
    unsigned long long r;
    asm("mov.b64 %0, {%1, %2};" : "=l"(r) : "r"(__float_as_uint(x)), "r"(__float_as_uint(y)));
    return r;
}
__device__ __forceinline__ void f2unpack(unsigned long long v, float& x, float& y) {
    unsigned int a, b;
    asm("mov.b64 {%0, %1}, %2;" : "=r"(a), "=r"(b) : "l"(v));
    x = __uint_as_float(a); y = __uint_as_float(b);
}
#define FMA_F32X2(d, a, b) asm("fma.rn.f32x2 %0, %1, %2, %0;" : "+l"(d) : "l"(a), "l"(b))

// ---------------- tiled SGEMM with packed f32x2 FMA (GEMM2) ----------------
template<int BM, int BN, int BK, int TM, int TN>
__global__ void k_gemm(const float* __restrict__ A, const float* __restrict__ B,
                       float* __restrict__ C, int M, int Ncols, int K) {
    constexpr int NT = (BM / TM) * (BN / TN);
    __shared__ float As[2][BK][BM];
    __shared__ float Bs[2][BK][BN];
    const int tid = threadIdx.x;
    const int tx = tid % (BN / TN);
    const int ty = tid / (BN / TN);
    const int row0 = blockIdx.y * BM;
    const int col0 = blockIdx.x * BN;

    auto loadA = [&](int buf, int kk) {
#pragma unroll
        for (int i = 0; i < (BM * BK) / (4 * NT); i++) {
            int idx = (tid + i * NT) * 4;
            int r = idx / BK;
            int kq = idx % BK;
            int grow = row0 + r;
            float4 v = make_float4(0.f, 0.f, 0.f, 0.f);
            if (grow < M)
                v = *reinterpret_cast<const float4*>(&A[(size_t)grow * K + kk + kq]);
            As[buf][kq + 0][r] = v.x;
            As[buf][kq + 1][r] = v.y;
            As[buf][kq + 2][r] = v.z;
            As[buf][kq + 3][r] = v.w;
        }
    };
    auto loadB = [&](int buf, int kk) {
#pragma unroll
        for (int i = 0; i < (BK * BN) / (4 * NT); i++) {
            int idx = (tid + i * NT) * 4;
            int kr = idx / BN;
            int c = idx % BN;
            *reinterpret_cast<float4*>(&Bs[buf][kr][c]) =
                *reinterpret_cast<const float4*>(&B[(size_t)(kk + kr) * Ncols + col0 + c]);
        }
    };

    unsigned long long acc[TM][TN / 2];
#pragma unroll
    for (int m = 0; m < TM; m++)
#pragma unroll
        for (int n = 0; n < TN / 2; n++) acc[m][n] = 0ull;

    loadA(0, 0); loadB(0, 0);
    __syncthreads();
    const int KT = K / BK;
    for (int kt = 0; kt < KT; kt++) {
        int cur = kt & 1;
        if (kt + 1 < KT) { loadA(cur ^ 1, (kt + 1) * BK); loadB(cur ^ 1, (kt + 1) * BK); }
#pragma unroll
        for (int kk = 0; kk < BK; kk++) {
            unsigned long long a2[TM], b2[TN / 2];
#pragma unroll
            for (int m = 0; m < TM; m++) {
                float a = As[cur][kk][ty * TM + m];
                a2[m] = f2pack(a, a);
            }
#pragma unroll
            for (int n = 0; n < TN / 2; n++) {
                float2 bv = *reinterpret_cast<const float2*>(&Bs[cur][kk][tx * TN + 2 * n]);
                b2[n] = f2pack(bv.x, bv.y);
            }
#pragma unroll
            for (int m = 0; m < TM; m++)
#pragma unroll
                for (int n = 0; n < TN / 2; n++)
                    FMA_F32X2(acc[m][n], a2[m], b2[n]);
        }
        __syncthreads();
    }
#pragma unroll
    for (int m = 0; m < TM; m++) {
        int grow = row0 + ty * TM + m;
        if (grow < M) {
#pragma unroll
            for (int n = 0; n < TN / 2; n++) {
                float x, y; f2unpack(acc[m][n], x, y);
                *reinterpret_cast<float2*>(&C[(size_t)grow * Ncols + col0 + tx * TN + 2 * n]) =
                    make_float2(x, y);
            }
        }
    }
}

// ---------------- layer1 attention logits: warp per node -------------------
__global__ void k_logits1(const float* __restrict__ asrc, const float* __restrict__ adst) {
    int w = (blockIdx.x * blockDim.x + threadIdx.x) >> 5;
    int lane = threadIdx.x & 31;
    if (w >= NN) return;
    const float4* hp = reinterpret_cast<const float4*>(&g_h1[(size_t)w * DHID + lane * 8]);
    float4 v0 = hp[0], v1 = hp[1];
    const float4* sp = reinterpret_cast<const float4*>(&asrc[lane * 8]);
    const float4* dp = reinterpret_cast<const float4*>(&adst[lane * 8]);
    float4 s0 = sp[0], s1 = sp[1], d0 = dp[0], d1 = dp[1];
    float ss = v0.x * s0.x + v0.y * s0.y + v0.z * s0.z + v0.w * s0.w
             + v1.x * s1.x + v1.y * s1.y + v1.z * s1.z + v1.w * s1.w;
    float sd = v0.x * d0.x + v0.y * d0.y + v0.z * d0.z + v0.w * d0.w
             + v1.x * d1.x + v1.y * d1.y + v1.z * d1.z + v1.w * d1.w;
#pragma unroll
    for (int off = 4; off > 0; off >>= 1) {
        ss += __shfl_xor_sync(0xffffffffu, ss, off);
        sd += __shfl_xor_sync(0xffffffffu, sd, off);
    }
    if ((lane & 7) == 0) {
        int head = lane >> 3;
        g_als1[w * NH + head] = ss;
        g_ald1[w * NH + head] = sd;
    }
}

// ---------------- layer1 edge exp + denominator ----------------------------
__global__ void k_exp1(const int* __restrict__ src, const int* __restrict__ dst) {
    int e = blockIdx.x * blockDim.x + threadIdx.x;
    if (e >= NE) return;
    int s = src[e], d = dst[e];
#pragma unroll
    for (int h = 0; h < NH; h++) {
        float v = g_als1[s * NH + h] + g_ald1[d * NH + h];
        v = v > 0.f ? v : NEG * v;
        float ex = expf(v);
        g_exp1[(size_t)e * NH + h] = ex;
        atomicAdd(&g_den1[d * NH + h], ex);
    }
}
__global__ void k_invden1() {
    int i = blockIdx.x * blockDim.x + threadIdx.x;
    if (i < NN * NH) g_den1[i] = 1.f / g_den1[i];
}

// ---------------- layer1 aggregation: 64 threads/edge, float4 atomics ------
__global__ void k_agg1(const int* __restrict__ src, const int* __restrict__ dst) {
    int t = blockIdx.x * blockDim.x + threadIdx.x;
    int e = t >> 6;
    int sub = t & 63;
    if (e >= NE) return;
    int s = src[e], d = dst[e];
    int head = sub >> 4;
    float alpha = g_exp1[(size_t)e * NH + head] * g_den1[d * NH + head];
    float4 v = *reinterpret_cast<const float4*>(&g_h1[(size_t)s * DHID + sub * 4]);
    v.x *= alpha; v.y *= alpha; v.z *= alpha; v.w *= alpha;
    atomicAdd(reinterpret_cast<float4*>(&g_agg1[(size_t)d * DHID + sub * 4]), v);
}

// ---------------- LayerNorm(256) + ELU, warp per node, writes into g_h1 ----
__global__ void k_ln1(const float* __restrict__ bias, const float* __restrict__ g,
                      const float* __restrict__ be) {
    int w = (blockIdx.x * blockDim.x + threadIdx.x) >> 5;
    int lane = threadIdx.x & 31;
    if (w >= NN) return;
    const float4* p = reinterpret_cast<const float4*>(&g_agg1[(size_t)w * DHID + lane * 8]);
    const float4* bp = reinterpret_cast<const float4*>(&bias[lane * 8]);
    float4 v0 = p[0], v1 = p[1];
    float4 b0 = bp[0], b1v = bp[1];
    v0.x += b0.x; v0.y += b0.y; v0.z += b0.z; v0.w += b0.w;
    v1.x += b1v.x; v1.y += b1v.y; v1.z += b1v.z; v1.w += b1v.w;
    float s  = v0.x + v0.y + v0.z + v0.w + v1.x + v1.y + v1.z + v1.w;
    float sq = v0.x * v0.x + v0.y * v0.y + v0.z * v0.z + v0.w * v0.w
             + v1.x * v1.x + v1.y * v1.y + v1.z * v1.z + v1.w * v1.w;
#pragma unroll
    for (int off = 16; off > 0; off >>= 1) {
        s  += __shfl_xor_sync(0xffffffffu, s, off);
        sq += __shfl_xor_sync(0xffffffffu, sq, off);
    }
    float mu = s * (1.f / DHID);
    float var = sq * (1.f / DHID) - mu * mu;
    float rstd = rsqrtf(var + LNEPS);
    const float4* gp = reinterpret_cast<const float4*>(&g[lane * 8]);
    const float4* ep = reinterpret_cast<const float4*>(&be[lane * 8]);
    float4 g0 = gp[0], g1v = gp[1], e0 = ep[0], e1 = ep[1];
    float out[8];
    float in[8]  = {v0.x, v0.y, v0.z, v0.w, v1.x, v1.y, v1.z, v1.w};
    float gg[8]  = {g0.x, g0.y, g0.z, g0.w, g1v.x, g1v.y, g1v.z, g1v.w};
    float bb[8]  = {e0.x, e0.y, e0.z, e0.w, e1.x, e1.y, e1.z, e1.w};
#pragma unroll
    for (int i = 0; i < 8; i++) {
        float y = (in[i] - mu) * rstd * gg[i] + bb[i];
        out[i] = y > 0.f ? y : expm1f(y);
    }
    float4* op = reinterpret_cast<float4*>(&g_h1[(size_t)w * DHID + lane * 8]);
    op[0] = make_float4(out[0], out[1], out[2], out[3]);
    op[1] = make_float4(out[4], out[5], out[6], out[7]);
}

// ---------------- layer2 attention logits: warp per node -------------------
__global__ void k_logits2(const float* __restrict__ asrc, const float* __restrict__ adst) {
    int w = (blockIdx.x * blockDim.x + threadIdx.x) >> 5;
    int lane = threadIdx.x & 31;
    if (w >= NN) return;
    float2 v = *reinterpret_cast<const float2*>(&g_h2[(size_t)w * DOUT + lane * 2]);
    float2 a = *reinterpret_cast<const float2*>(&asrc[lane * 2]);
    float2 b = *reinterpret_cast<const float2*>(&adst[lane * 2]);
    float ss = v.x * a.x + v.y * a.y;
    float sd = v.x * b.x + v.y * b.y;
#pragma unroll
    for (int off = 16; off > 0; off >>= 1) {
        ss += __shfl_xor_sync(0xffffffffu, ss, off);
        sd += __shfl_xor_sync(0xffffffffu, sd, off);
    }
    if (lane == 0) { g_als2[w] = ss; g_ald2[w] = sd; }
}

__global__ void k_exp2(const int* __restrict__ src, const int* __restrict__ dst) {
    int e = blockIdx.x * blockDim.x + threadIdx.x;
    if (e >= NE) return;
    int s = src[e], d = dst[e];
    float v = g_als2[s] + g_ald2[d];
    v = v > 0.f ? v : NEG * v;
    float ex = expf(v);
    g_exp2[e] = ex;
    atomicAdd(&g_den2[d], ex);
}
__global__ void k_invden2() {
    int i = blockIdx.x * blockDim.x + threadIdx.x;
    if (i < NN) g_den2[i] = 1.f / g_den2[i];
}

// ---------------- layer2 aggregation: 16 threads/edge ----------------------
__global__ void k_agg2(const int* __restrict__ src, const int* __restrict__ dst) {
    int t = blockIdx.x * blockDim.x + threadIdx.x;
    int e = t >> 4;
    int sub = t & 15;
    if (e >= NE) return;
    int s = src[e], d = dst[e];
    float alpha = g_exp2[e] * g_den2[d];
    float4 v = *reinterpret_cast<const float4*>(&g_h2[(size_t)s * DOUT + sub * 4]);
    v.x *= alpha; v.y *= alpha; v.z *= alpha; v.w *= alpha;
    atomicAdd(reinterpret_cast<float4*>(&g_agg2[(size_t)d * DOUT + sub * 4]), v);
}

// ---------------- final LayerNorm(64) -> d_out -----------------------------
__global__ void k_ln2(const float* __restrict__ bias, const float* __restrict__ g,
                      const float* __restrict__ be, float* __restrict__ out) {
    int w = (blockIdx.x * blockDim.x + threadIdx.x) >> 5;
    int lane = threadIdx.x & 31;
    if (w >= NN) return;
    float2 v = *reinterpret_cast<const float2*>(&g_agg2[(size_t)w * DOUT + lane * 2]);
    float2 b = *reinterpret_cast<const float2*>(&bias[lane * 2]);
    v.x += b.x; v.y += b.y;
    float s = v.x + v.y;
    float sq = v.x * v.x + v.y * v.y;
#pragma unroll
    for (int off = 16; off > 0; off >>= 1) {
        s  += __shfl_xor_sync(0xffffffffu, s, off);
        sq += __shfl_xor_sync(0xffffffffu, sq, off);
    }
    float mu = s * (1.f / DOUT);
    float var = sq * (1.f / DOUT) - mu * mu;
    float rstd = rsqrtf(var + LNEPS);
    float2 gg = *reinterpret_cast<const float2*>(&g[lane * 2]);
    float2 bb = *reinterpret_cast<const float2*>(&be[lane * 2]);
    float2 o;
    o.x = (v.x - mu) * rstd * gg.x + bb.x;
    o.y = (v.y - mu) * rstd * gg.y + bb.y;
    *reinterpret_cast<float2*>(&out[(size_t)w * DOUT + lane * 2]) = o;
}

// ---------------- host launch ----------------------------------------------
extern "C" void kernel_launch(void* const* d_in, const int* in_sizes, int n_in,
                              void* d_out, int out_size) {
    const float* x    = (const float*)d_in[0];
    const int*   ei   = (const int*)d_in[1];   // [2, E]: row0 = src, row1 = dst
    const int*   et   = (const int*)d_in[2];
    const float* emb  = (const float*)d_in[3];
    const float* W1   = (const float*)d_in[4];
    const float* as1  = (const float*)d_in[5];
    const float* ad1  = (const float*)d_in[6];
    const float* b1   = (const float*)d_in[7];
    const float* g1   = (const float*)d_in[8];
    const float* be1  = (const float*)d_in[9];
    const float* W2   = (const float*)d_in[10];
    const float* as2  = (const float*)d_in[11];
    const float* ad2  = (const float*)d_in[12];
    const float* b2   = (const float*)d_in[13];
    const float* g2   = (const float*)d_in[14];
    const float* be2  = (const float*)d_in[15];
    float* out = (float*)d_out;

    const int* src = ei;
    const int* dst = ei + NE;

    void *p_h1, *p_h2;
    cudaGetSymbolAddress(&p_h1, g_h1);
    cudaGetSymbolAddress(&p_h2, g_h2);

    cudaFuncSetAttribute(k_gemm1_mma, cudaFuncAttributeMaxDynamicSharedMemorySize, G1_SMEM);

    // 1. init scratch
    k_init<<<2048, 256>>>();
    // 2. last-write-wins relation per src node
    k_winner<<<(NE + 255) / 256, 256>>>(src);
    k_rel<<<(NN + 255) / 256, 256>>>(et);
    // 3. GEMM1 via mma.sync bf16-split: (x + emb[rel]) @ W1 -> g_h1  [50000 x 256]
    {
        dim3 grid(DHID / 128, (NN + 127) / 128);   // (2, 391)
        k_gemm1_mma<<<grid, 256, G1_SMEM>>>(x, emb, W1);
    }
    // 4. attention layer 1
    k_logits1<<<(NN * 32) / 256, 256>>>(as1, ad1);
    k_exp1<<<(NE + 255) / 256, 256>>>(src, dst);
    k_invden1<<<(NN * NH + 255) / 256, 256>>>();
    k_agg1<<<(NE * 64) / 256, 256>>>(src, dst);
    // 5. LN + ELU -> g_h1 (reuse)
    k_ln1<<<(NN * 32) / 256, 256>>>(b1, g1, be1);
    // 6. GEMM2: h @ W2 -> g_h2  [50000 x 64]
    {
        dim3 grid(DOUT / 64, (NN + 127) / 128);
        k_gemm<128, 64, 16, 8, 8><<<grid, 128>>>(
            (const float*)p_h1, W2, (float*)p_h2, NN, DOUT, DHID);
    }
    // 7. attention layer 2
    k_logits2<<<(NN * 32) / 256, 256>>>(as2, ad2);
    k_exp2<<<(NE + 255) / 256, 256>>>(src, dst);
    k_invden2<<<(NN + 255) / 256, 256>>>();
    k_agg2<<<(NE * 16) / 256, 256>>>(src, dst);
    // 8. final LayerNorm -> d_out
    k_ln2<<<(NN * 32) / 256, 256>>>(b2, g2, be2, out);
}

// round 10
// speedup vs baseline: 1.9415x; 1.7163x over previous
#include <cuda_runtime.h>
#include <cuda_bf16.h>
#include <math.h>
#include <stdint.h>

// ---------------- problem constants ----------------
#define NN 50000      // nodes
#define NE 200000     // edges
#define DIN 768
#define DHID 256
#define DOUT 64
#define NH 4          // heads layer1
#define NEG 0.2f
#define LNEPS 1e-5f

// ---------------- scratch (device globals; no allocation allowed) ----------
__device__ float g_h1[(size_t)NN * DHID];
__device__ float g_agg1[(size_t)NN * DHID];
__device__ float g_h2[(size_t)NN * DOUT];
__device__ float g_agg2[(size_t)NN * DOUT];
__device__ float g_als1[NN * NH];
__device__ float g_ald1[NN * NH];
__device__ float g_den1[NN * NH];
__device__ float g_als2[NN];
__device__ float g_ald2[NN];
__device__ float g_den2[NN];
__device__ float g_exp1[(size_t)NE * NH];
__device__ float g_exp2[NE];
__device__ int   g_rel[NN];
// bf16 hi/lo splits of (x + emb[rel]) and W1
__device__ uint16_t g_xh[(size_t)NN * DIN];
__device__ uint16_t g_xl[(size_t)NN * DIN];
__device__ uint16_t g_w1h[(size_t)DIN * DHID];
__device__ uint16_t g_w1l[(size_t)DIN * DHID];

// ---------------- helpers ---------------------------------------------------
__device__ __forceinline__ uint32_t s2u(const void* p) {
    uint32_t a;
    asm("{ .reg .u64 t; cvta.to.shared.u64 t, %1; cvt.u32.u64 %0, t; }" : "=r"(a) : "l"(p));
    return a;
}
// split float pair into bf16-hi pair (packed) and bf16-lo residual pair
__device__ __forceinline__ void cvt_split2(float e0, float e1, uint32_t& ph, uint32_t& pl) {
    asm("cvt.rn.bf16x2.f32 %0, %1, %2;" : "=r"(ph) : "f"(e1), "f"(e0));
    float h0 = __uint_as_float(ph << 16);
    float h1 = __uint_as_float(ph & 0xffff0000u);
    float l0 = e0 - h0, l1 = e1 - h1;
    asm("cvt.rn.bf16x2.f32 %0, %1, %2;" : "=r"(pl) : "f"(l1), "f"(l0));
}

#define LDSM4(d, addr) \
    asm volatile("ldmatrix.sync.aligned.m8n8.x4.shared.b16 {%0,%1,%2,%3}, [%4];" \
        : "=r"((d)[0]), "=r"((d)[1]), "=r"((d)[2]), "=r"((d)[3]) : "r"(addr))
#define LDSM4T(d, addr) \
    asm volatile("ldmatrix.sync.aligned.m8n8.x4.trans.shared.b16 {%0,%1,%2,%3}, [%4];" \
        : "=r"((d)[0]), "=r"((d)[1]), "=r"((d)[2]), "=r"((d)[3]) : "r"(addr))
#define MMA_BF16(c, a, b0, b1) \
    asm volatile("mma.sync.aligned.m16n8k16.row.col.f32.bf16.bf16.f32 " \
        "{%0,%1,%2,%3}, {%4,%5,%6,%7}, {%8,%9}, {%0,%1,%2,%3};" \
        : "+f"((c)[0]), "+f"((c)[1]), "+f"((c)[2]), "+f"((c)[3]) \
        : "r"((a)[0]), "r"((a)[1]), "r"((a)[2]), "r"((a)[3]), "r"(b0), "r"(b1))
#define CP_ASYNC16(saddr, gptr) \
    asm volatile("cp.async.cg.shared.global [%0], [%1], 16;" \
        :: "r"(saddr), "l"(gptr) : "memory")
#define CP_COMMIT() asm volatile("cp.async.commit_group;" ::: "memory")
#define CP_WAIT1()  asm volatile("cp.async.wait_group 1;" ::: "memory")

// ---------------- init: zero accumulators, winner = -1 ---------------------
__global__ void k_init() {
    int i = blockIdx.x * blockDim.x + threadIdx.x;
    int stride = gridDim.x * blockDim.x;
    for (int j = i; j < NN * DHID; j += stride) g_agg1[j] = 0.f;
    for (int j = i; j < NN * DOUT; j += stride) g_agg2[j] = 0.f;
    for (int j = i; j < NN * NH;   j += stride) g_den1[j] = 0.f;
    for (int j = i; j < NN;        j += stride) { g_den2[j] = 0.f; g_rel[j] = -1; }
}

// winner[src[e]] = max edge id (deterministic "last write wins")
__global__ void k_winner(const int* __restrict__ src) {
    int e = blockIdx.x * blockDim.x + threadIdx.x;
    if (e < NE) atomicMax(&g_rel[src[e]], e);
}
__global__ void k_rel(const int* __restrict__ etype) {
    int n = blockIdx.x * blockDim.x + threadIdx.x;
    if (n < NN) { int w = g_rel[n]; g_rel[n] = (w < 0) ? -1 : etype[w]; }
}

// ---------------- pre-split: (x + emb[rel]) -> bf16 hi/lo ------------------
__global__ void k_split(const float* __restrict__ x, const float* __restrict__ emb) {
    int f = blockIdx.x * blockDim.x + threadIdx.x;   // float4 index
    if (f >= NN * (DIN / 4)) return;
    int row = f / (DIN / 4), c4 = f % (DIN / 4);
    float4 v = *reinterpret_cast<const float4*>(&x[(size_t)row * DIN + c4 * 4]);
    int rl = g_rel[row];
    if (rl >= 0) {
        float4 e = *reinterpret_cast<const float4*>(&emb[(size_t)rl * DIN + c4 * 4]);
        v.x += e.x; v.y += e.y; v.z += e.z; v.w += e.w;
    }
    uint32_t h0, l0, h1, l1;
    cvt_split2(v.x, v.y, h0, l0);
    cvt_split2(v.z, v.w, h1, l1);
    size_t o = (size_t)row * DIN + c4 * 4;
    *reinterpret_cast<uint2*>(&g_xh[o]) = make_uint2(h0, h1);
    *reinterpret_cast<uint2*>(&g_xl[o]) = make_uint2(l0, l1);
}
__global__ void k_splitW(const float* __restrict__ W1) {
    int f = blockIdx.x * blockDim.x + threadIdx.x;
    if (f >= (DIN * DHID) / 4) return;
    float4 v = *reinterpret_cast<const float4*>(&W1[(size_t)f * 4]);
    uint32_t h0, l0, h1, l1;
    cvt_split2(v.x, v.y, h0, l0);
    cvt_split2(v.z, v.w, h1, l1);
    *reinterpret_cast<uint2*>(&g_w1h[(size_t)f * 4]) = make_uint2(h0, h1);
    *reinterpret_cast<uint2*>(&g_w1l[(size_t)f * 4]) = make_uint2(l0, l1);
}

// ---------------- GEMM1: 128x256 tiles, cp.async 3-stage, bf16-split MMA ---
#define AST 80                         // A smem row stride (64B data + 16 pad)
#define BST 528                        // B smem row stride (512B data + 16 pad)
#define ATILE (128 * AST)              // 10240
#define BTILE (32 * BST)               // 16896
#define STAGE_B (2 * ATILE + 2 * BTILE)  // 54272
#define NSTAGE 3
#define G1_SMEM (NSTAGE * STAGE_B)       // 162816

__global__ void __launch_bounds__(512, 1) k_gemm1_mma() {
    extern __shared__ char smem[];
    const uint32_t sb = s2u(smem);
    const int tid = threadIdx.x;
    const int wid = tid >> 5, lane = tid & 31;
    const int warp_m = wid >> 2;      // 0..3 -> 32-row slice
    const int warp_n = wid & 3;       // 0..3 -> 64-col slice
    const int m0 = blockIdx.x * 128;

    // cp.async source/dest mapping (per thread, fixed struct per chunk)
    // A: one 16B chunk each for hi & lo: r = tid>>2 (0..127), c = tid&3 (0..3)
    const int ar = tid >> 2, ac = tid & 3;
    int arow = m0 + ar; if (arow >= NN) arow = 0;           // clamp; epilogue guards
    const uint16_t* axh = &g_xh[(size_t)arow * DIN + ac * 8];
    const uint16_t* axl = &g_xl[(size_t)arow * DIN + ac * 8];
    const uint32_t a_sts = (uint32_t)(ar * AST + ac * 16);
    // B: two chunks each for hi & lo: idx = tid + i*512, k = idx>>5, c = idx&31
    const int bk0 = tid >> 5, bc0 = tid & 31;       // i=0
    const int bk1 = (tid + 512) >> 5, bc1 = tid & 31; // i=1
    const uint32_t b_sts0 = (uint32_t)(bk0 * BST + bc0 * 16);
    const uint32_t b_sts1 = (uint32_t)(bk1 * BST + bc1 * 16);

    auto issue = [&](int kt, int st) {
        uint32_t base = sb + (uint32_t)st * STAGE_B;
        int k0 = kt * 32;
        CP_ASYNC16(base + a_sts, axh + k0);
        CP_ASYNC16(base + ATILE + a_sts, axl + k0);
        const uint16_t* wh = &g_w1h[(size_t)k0 * DHID];
        const uint16_t* wl = &g_w1l[(size_t)k0 * DHID];
        CP_ASYNC16(base + 2 * ATILE + b_sts0, wh + (size_t)bk0 * DHID + bc0 * 8);
        CP_ASYNC16(base + 2 * ATILE + b_sts1, wh + (size_t)bk1 * DHID + bc1 * 8);
        CP_ASYNC16(base + 2 * ATILE + BTILE + b_sts0, wl + (size_t)bk0 * DHID + bc0 * 8);
        CP_ASYNC16(base + 2 * ATILE + BTILE + b_sts1, wl + (size_t)bk1 * DHID + bc1 * 8);
    };

    // ldmatrix per-lane bases
    const uint32_t a_lm = (uint32_t)((warp_m * 32 + (lane & 15)) * AST + (lane >> 4) * 16);
    const uint32_t b_lm = (uint32_t)((lane & 15) * BST + (warp_n * 64 + (lane >> 4) * 8) * 2);

    float acc[2][8][4];
#pragma unroll
    for (int mi = 0; mi < 2; mi++)
#pragma unroll
        for (int nf = 0; nf < 8; nf++)
#pragma unroll
            for (int j = 0; j < 4; j++) acc[mi][nf][j] = 0.f;

    issue(0, 0); CP_COMMIT();
    issue(1, 1); CP_COMMIT();

    const int NCHUNK = DIN / 32;   // 24
    for (int kt = 0; kt < NCHUNK; kt++) {
        const int st = kt % NSTAGE;
        CP_WAIT1();
        __syncthreads();
        const uint32_t base = sb + (uint32_t)st * STAGE_B;
        const uint32_t sAh = base + a_lm;
        const uint32_t sAl = base + ATILE + a_lm;
        const uint32_t sBh = base + 2 * ATILE + b_lm;
        const uint32_t sBl = base + 2 * ATILE + BTILE + b_lm;
#pragma unroll
        for (int s = 0; s < 2; s++) {
            uint32_t ah[2][4], al[2][4];
            LDSM4(ah[0], sAh + s * 32);
            LDSM4(ah[1], sAh + 16 * AST + s * 32);
            LDSM4(al[0], sAl + s * 32);
            LDSM4(al[1], sAl + 16 * AST + s * 32);
#pragma unroll
            for (int g = 0; g < 4; g++) {
                uint32_t bh[4], bl[4];
                LDSM4T(bh, sBh + s * (16 * BST) + g * 32);
                LDSM4T(bl, sBl + s * (16 * BST) + g * 32);
#pragma unroll
                for (int mi = 0; mi < 2; mi++) {
                    MMA_BF16(acc[mi][2 * g],     ah[mi], bh[0], bh[1]);
                    MMA_BF16(acc[mi][2 * g],     al[mi], bh[0], bh[1]);
                    MMA_BF16(acc[mi][2 * g],     ah[mi], bl[0], bl[1]);
                    MMA_BF16(acc[mi][2 * g + 1], ah[mi], bh[2], bh[3]);
                    MMA_BF16(acc[mi][2 * g + 1], al[mi], bh[2], bh[3]);
                    MMA_BF16(acc[mi][2 * g + 1], ah[mi], bl[2], bl[3]);
                }
            }
        }
        if (kt + 2 < NCHUNK) issue(kt + 2, (kt + 2) % NSTAGE);
        CP_COMMIT();   // unconditional: keeps wait_group accounting correct
    }

    // epilogue
#pragma unroll
    for (int mi = 0; mi < 2; mi++) {
        int r0 = m0 + warp_m * 32 + mi * 16 + (lane >> 2);
#pragma unroll
        for (int nf = 0; nf < 8; nf++) {
            int c = warp_n * 64 + nf * 8 + (lane & 3) * 2;
            if (r0 < NN)
                *reinterpret_cast<float2*>(&g_h1[(size_t)r0 * DHID + c]) =
                    make_float2(acc[mi][nf][0], acc[mi][nf][1]);
            if (r0 + 8 < NN)
                *reinterpret_cast<float2*>(&g_h1[(size_t)(r0 + 8) * DHID + c]) =
                    make_float2(acc[mi][nf][2], acc[mi][nf][3]);
        }
    }
}

// ---------------- f32x2 packed-FMA helpers (GEMM2) -------------------------
__device__ __forceinline__ unsigned long long f2pack(float x, float y) {
    unsigned long long r;
    asm("mov.b64 %0, {%1, %2};" : "=l"(r) : "r"(__float_as_uint(x)), "r"(__float_as_uint(y)));
    return r;
}
__device__ __forceinline__ void f2unpack(unsigned long long v, float& x, float& y) {
    unsigned int a, b;
    asm("mov.b64 {%0, %1}, %2;" : "=r"(a), "=r"(b) : "l"(v));
    x = __uint_as_float(a); y = __uint_as_float(b);
}
#define FMA_F32X2(d, a, b) asm("fma.rn.f32x2 %0, %1, %2, %0;" : "+l"(d) : "l"(a), "l"(b))

template<int BM, int BN, int BK, int TM, int TN>
__global__ void k_gemm(const float* __restrict__ A, const float* __restrict__ B,
                       float* __restrict__ C, int M, int Ncols, int K) {
    constexpr int NT = (BM / TM) * (BN / TN);
    __shared__ float As[2][BK][BM];
    __shared__ float Bs[2][BK][BN];
    const int tid = threadIdx.x;
    const int tx = tid % (BN / TN);
    const int ty = tid / (BN / TN);
    const int row0 = blockIdx.y * BM;
    const int col0 = blockIdx.x * BN;

    auto loadA = [&](int buf, int kk) {
#pragma unroll
        for (int i = 0; i < (BM * BK) / (4 * NT); i++) {
            int idx = (tid + i * NT) * 4;
            int r = idx / BK;
            int kq = idx % BK;
            int grow = row0 + r;
            float4 v = make_float4(0.f, 0.f, 0.f, 0.f);
            if (grow < M)
                v = *reinterpret_cast<const float4*>(&A[(size_t)grow * K + kk + kq]);
            As[buf][kq + 0][r] = v.x;
            As[buf][kq + 1][r] = v.y;
            As[buf][kq + 2][r] = v.z;
            As[buf][kq + 3][r] = v.w;
        }
    };
    auto loadB = [&](int buf, int kk) {
#pragma unroll
        for (int i = 0; i < (BK * BN) / (4 * NT); i++) {
            int idx = (tid + i * NT) * 4;
            int kr = idx / BN;
            int c = idx % BN;
            *reinterpret_cast<float4*>(&Bs[buf][kr][c]) =
                *reinterpret_cast<const float4*>(&B[(size_t)(kk + kr) * Ncols + col0 + c]);
        }
    };

    unsigned long long acc[TM][TN / 2];
#pragma unroll
    for (int m = 0; m < TM; m++)
#pragma unroll
        for (int n = 0; n < TN / 2; n++) acc[m][n] = 0ull;

    loadA(0, 0); loadB(0, 0);
    __syncthreads();
    const int KT = K / BK;
    for (int kt = 0; kt < KT; kt++) {
        int cur = kt & 1;
        if (kt + 1 < KT) { loadA(cur ^ 1, (kt + 1) * BK); loadB(cur ^ 1, (kt + 1) * BK); }
#pragma unroll
        for (int kk = 0; kk < BK; kk++) {
            unsigned long long a2[TM], b2[TN / 2];
#pragma unroll
            for (int m = 0; m < TM; m++) {
                float a = As[cur][kk][ty * TM + m];
                a2[m] = f2pack(a, a);
            }
#pragma unroll
            for (int n = 0; n < TN / 2; n++) {
                float2 bv = *reinterpret_cast<const float2*>(&Bs[cur][kk][tx * TN + 2 * n]);
                b2[n] = f2pack(bv.x, bv.y);
            }
#pragma unroll
            for (int m = 0; m < TM; m++)
#pragma unroll
                for (int n = 0; n < TN / 2; n++)
                    FMA_F32X2(acc[m][n], a2[m], b2[n]);
        }
        __syncthreads();
    }
#pragma unroll
    for (int m = 0; m < TM; m++) {
        int grow = row0 + ty * TM + m;
        if (grow < M) {
#pragma unroll
            for (int n = 0; n < TN / 2; n++) {
                float x, y; f2unpack(acc[m][n], x, y);
                *reinterpret_cast<float2*>(&C[(size_t)grow * Ncols + col0 + tx * TN + 2 * n]) =
                    make_float2(x, y);
            }
        }
    }
}

// ---------------- layer1 attention logits: warp per node -------------------
__global__ void k_logits1(const float* __restrict__ asrc, const float* __restrict__ adst) {
    int w = (blockIdx.x * blockDim.x + threadIdx.x) >> 5;
    int lane = threadIdx.x & 31;
    if (w >= NN) return;
    const float4* hp = reinterpret_cast<const float4*>(&g_h1[(size_t)w * DHID + lane * 8]);
    float4 v0 = hp[0], v1 = hp[1];
    const float4* sp = reinterpret_cast<const float4*>(&asrc[lane * 8]);
    const float4* dp = reinterpret_cast<const float4*>(&adst[lane * 8]);
    float4 s0 = sp[0], s1 = sp[1], d0 = dp[0], d1 = dp[1];
    float ss = v0.x * s0.x + v0.y * s0.y + v0.z * s0.z + v0.w * s0.w
             + v1.x * s1.x + v1.y * s1.y + v1.z * s1.z + v1.w * s1.w;
    float sd = v0.x * d0.x + v0.y * d0.y + v0.z * d0.z + v0.w * d0.w
             + v1.x * d1.x + v1.y * d1.y + v1.z * d1.z + v1.w * d1.w;
#pragma unroll
    for (int off = 4; off > 0; off >>= 1) {
        ss += __shfl_xor_sync(0xffffffffu, ss, off);
        sd += __shfl_xor_sync(0xffffffffu, sd, off);
    }
    if ((lane & 7) == 0) {
        int head = lane >> 3;
        g_als1[w * NH + head] = ss;
        g_ald1[w * NH + head] = sd;
    }
}

// ---------------- layer1 edge exp + denominator (vec4 atomic) --------------
__global__ void k_exp1(const int* __restrict__ src, const int* __restrict__ dst) {
    int e = blockIdx.x * blockDim.x + threadIdx.x;
    if (e >= NE) return;
    int s = src[e], d = dst[e];
    float4 as = *reinterpret_cast<const float4*>(&g_als1[s * NH]);
    float4 ad = *reinterpret_cast<const float4*>(&g_ald1[d * NH]);
    float4 ex;
    float v;
    v = as.x + ad.x; v = v > 0.f ? v : NEG * v; ex.x = expf(v);
    v = as.y + ad.y; v = v > 0.f ? v : NEG * v; ex.y = expf(v);
    v = as.z + ad.z; v = v > 0.f ? v : NEG * v; ex.z = expf(v);
    v = as.w + ad.w; v = v > 0.f ? v : NEG * v; ex.w = expf(v);
    *reinterpret_cast<float4*>(&g_exp1[(size_t)e * NH]) = ex;
    atomicAdd(reinterpret_cast<float4*>(&g_den1[d * NH]), ex);
}
__global__ void k_invden1() {
    int i = blockIdx.x * blockDim.x + threadIdx.x;
    if (i < NN * NH) g_den1[i] = 1.f / g_den1[i];
}

// ---------------- layer1 aggregation: 64 threads/edge, float4 atomics ------
__global__ void k_agg1(const int* __restrict__ src, const int* __restrict__ dst) {
    int t = blockIdx.x * blockDim.x + threadIdx.x;
    int e = t >> 6;
    int sub = t & 63;
    if (e >= NE) return;
    int s = src[e], d = dst[e];
    int head = sub >> 4;
    float alpha = g_exp1[(size_t)e * NH + head] * g_den1[d * NH + head];
    float4 v = *reinterpret_cast<const float4*>(&g_h1[(size_t)s * DHID + sub * 4]);
    v.x *= alpha; v.y *= alpha; v.z *= alpha; v.w *= alpha;
    atomicAdd(reinterpret_cast<float4*>(&g_agg1[(size_t)d * DHID + sub * 4]), v);
}

// ---------------- LayerNorm(256) + ELU, warp per node ----------------------
__global__ void k_ln1(const float* __restrict__ bias, const float* __restrict__ g,
                      const float* __restrict__ be) {
    int w = (blockIdx.x * blockDim.x + threadIdx.x) >> 5;
    int lane = threadIdx.x & 31;
    if (w >= NN) return;
    const float4* p = reinterpret_cast<const float4*>(&g_agg1[(size_t)w * DHID + lane * 8]);
    const float4* bp = reinterpret_cast<const float4*>(&bias[lane * 8]);
    float4 v0 = p[0], v1 = p[1];
    float4 b0 = bp[0], b1v = bp[1];
    v0.x += b0.x; v0.y += b0.y; v0.z += b0.z; v0.w += b0.w;
    v1.x += b1v.x; v1.y += b1v.y; v1.z += b1v.z; v1.w += b1v.w;
    float s  = v0.x + v0.y + v0.z + v0.w + v1.x + v1.y + v1.z + v1.w;
    float sq = v0.x * v0.x + v0.y * v0.y + v0.z * v0.z + v0.w * v0.w
             + v1.x * v1.x + v1.y * v1.y + v1.z * v1.z + v1.w * v1.w;
#pragma unroll
    for (int off = 16; off > 0; off >>= 1) {
        s  += __shfl_xor_sync(0xffffffffu, s, off);
        sq += __shfl_xor_sync(0xffffffffu, sq, off);
    }
    float mu = s * (1.f / DHID);
    float var = sq * (1.f / DHID) - mu * mu;
    float rstd = rsqrtf(var + LNEPS);
    const float4* gp = reinterpret_cast<const float4*>(&g[lane * 8]);
    const float4* ep = reinterpret_cast<const float4*>(&be[lane * 8]);
    float4 g0 = gp[0], g1v = gp[1], e0 = ep[0], e1 = ep[1];
    float out[8];
    float in[8]  = {v0.x, v0.y, v0.z, v0.w, v1.x, v1.y, v1.z, v1.w};
    float gg[8]  = {g0.x, g0.y, g0.z, g0.w, g1v.x, g1v.y, g1v.z, g1v.w};
    float bb[8]  = {e0.x, e0.y, e0.z, e0.w, e1.x, e1.y, e1.z, e1.w};
#pragma unroll
    for (int i = 0; i < 8; i++) {
        float y = (in[i] - mu) * rstd * gg[i] + bb[i];
        out[i] = y > 0.f ? y : expm1f(y);
    }
    float4* op = reinterpret_cast<float4*>(&g_h1[(size_t)w * DHID + lane * 8]);
    op[0] = make_float4(out[0], out[1], out[2], out[3]);
    op[1] = make_float4(out[4], out[5], out[6], out[7]);
}

// ---------------- layer2 attention logits ----------------------------------
__global__ void k_logits2(const float* __restrict__ asrc, const float* __restrict__ adst) {
    int w = (blockIdx.x * blockDim.x + threadIdx.x) >> 5;
    int lane = threadIdx.x & 31;
    if (w >= NN) return;
    float2 v = *reinterpret_cast<const float2*>(&g_h2[(size_t)w * DOUT + lane * 2]);
    float2 a = *reinterpret_cast<const float2*>(&asrc[lane * 2]);
    float2 b = *reinterpret_cast<const float2*>(&adst[lane * 2]);
    float ss = v.x * a.x + v.y * a.y;
    float sd = v.x * b.x + v.y * b.y;
#pragma unroll
    for (int off = 16; off > 0; off >>= 1) {
        ss += __shfl_xor_sync(0xffffffffu, ss, off);
        sd += __shfl_xor_sync(0xffffffffu, sd, off);
    }
    if (lane == 0) { g_als2[w] = ss; g_ald2[w] = sd; }
}

__global__ void k_exp2(const int* __restrict__ src, const int* __restrict__ dst) {
    int e = blockIdx.x * blockDim.x + threadIdx.x;
    if (e >= NE) return;
    int s = src[e], d = dst[e];
    float v = g_als2[s] + g_ald2[d];
    v = v > 0.f ? v : NEG * v;
    float ex = expf(v);
    g_exp2[e] = ex;
    atomicAdd(&g_den2[d], ex);
}
__global__ void k_invden2() {
    int i = blockIdx.x * blockDim.x + threadIdx.x;
    if (i < NN) g_den2[i] = 1.f / g_den2[i];
}

// ---------------- layer2 aggregation: 16 threads/edge ----------------------
__global__ void k_agg2(const int* __restrict__ src, const int* __restrict__ dst) {
    int t = blockIdx.x * blockDim.x + threadIdx.x;
    int e = t >> 4;
    int sub = t & 15;
    if (e >= NE) return;
    int s = src[e], d = dst[e];
    float alpha = g_exp2[e] * g_den2[d];
    float4 v = *reinterpret_cast<const float4*>(&g_h2[(size_t)s * DOUT + sub * 4]);
    v.x *= alpha; v.y *= alpha; v.z *= alpha; v.w *= alpha;
    atomicAdd(reinterpret_cast<float4*>(&g_agg2[(size_t)d * DOUT + sub * 4]), v);
}

// ---------------- final LayerNorm(64) -> d_out -----------------------------
__global__ void k_ln2(const float* __restrict__ bias, const float* __restrict__ g,
                      const float* __restrict__ be, float* __restrict__ out) {
    int w = (blockIdx.x * blockDim.x + threadIdx.x) >> 5;
    int lane = threadIdx.x & 31;
    if (w >= NN) return;
    float2 v = *reinterpret_cast<const float2*>(&g_agg2[(size_t)w * DOUT + lane * 2]);
    float2 b = *reinterpret_cast<const float2*>(&bias[lane * 2]);
    v.x += b.x; v.y += b.y;
    float s = v.x + v.y;
    float sq = v.x * v.x + v.y * v.y;
#pragma unroll
    for (int off = 16; off > 0; off >>= 1) {
        s  += __shfl_xor_sync(0xffffffffu, s, off);
        sq += __shfl_xor_sync(0xffffffffu, sq, off);
    }
    float mu = s * (1.f / DOUT);
    float var = sq * (1.f / DOUT) - mu * mu;
    float rstd = rsqrtf(var + LNEPS);
    float2 gg = *reinterpret_cast<const float2*>(&g[lane * 2]);
    float2 bb = *reinterpret_cast<const float2*>(&be[lane * 2]);
    float2 o;
    o.x = (v.x - mu) * rstd * gg.x + bb.x;
    o.y = (v.y - mu) * rstd * gg.y + bb.y;
    *reinterpret_cast<float2*>(&out[(size_t)w * DOUT + lane * 2]) = o;
}

// ---------------- host launch ----------------------------------------------
extern "C" void kernel_launch(void* const* d_in, const int* in_sizes, int n_in,
                              void* d_out, int out_size) {
    const float* x    = (const float*)d_in[0];
    const int*   ei   = (const int*)d_in[1];   // [2, E]: row0 = src, row1 = dst
    const int*   et   = (const int*)d_in[2];
    const float* emb  = (const float*)d_in[3];
    const float* W1   = (const float*)d_in[4];
    const float* as1  = (const float*)d_in[5];
    const float* ad1  = (const float*)d_in[6];
    const float* b1   = (const float*)d_in[7];
    const float* g1   = (const float*)d_in[8];
    const float* be1  = (const float*)d_in[9];
    const float* W2   = (const float*)d_in[10];
    const float* as2  = (const float*)d_in[11];
    const float* ad2  = (const float*)d_in[12];
    const float* b2   = (const float*)d_in[13];
    const float* g2   = (const float*)d_in[14];
    const float* be2  = (const float*)d_in[15];
    float* out = (float*)d_out;

    const int* src = ei;
    const int* dst = ei + NE;

    void *p_h1, *p_h2;
    cudaGetSymbolAddress(&p_h1, g_h1);
    cudaGetSymbolAddress(&p_h2, g_h2);

    cudaFuncSetAttribute(k_gemm1_mma, cudaFuncAttributeMaxDynamicSharedMemorySize, G1_SMEM);

    // 1. init scratch
    k_init<<<2048, 256>>>();
    // 2. last-write-wins relation per src node
    k_winner<<<(NE + 255) / 256, 256>>>(src);
    k_rel<<<(NN + 255) / 256, 256>>>(et);
    // 3. pre-split into bf16 hi/lo
    k_split<<<(NN * (DIN / 4) + 255) / 256, 256>>>(x, emb);
    k_splitW<<<((DIN * DHID) / 4 + 255) / 256, 256>>>(W1);
    // 4. GEMM1: (x + emb[rel]) @ W1 -> g_h1  [50000 x 256]
    k_gemm1_mma<<<(NN + 127) / 128, 512, G1_SMEM>>>();
    // 5. attention layer 1
    k_logits1<<<(NN * 32) / 256, 256>>>(as1, ad1);
    k_exp1<<<(NE + 255) / 256, 256>>>(src, dst);
    k_invden1<<<(NN * NH + 255) / 256, 256>>>();
    k_agg1<<<(NE * 64) / 256, 256>>>(src, dst);
    // 6. LN + ELU -> g_h1 (reuse)
    k_ln1<<<(NN * 32) / 256, 256>>>(b1, g1, be1);
    // 7. GEMM2: h @ W2 -> g_h2  [50000 x 64]
    {
        dim3 grid(DOUT / 64, (NN + 127) / 128);
        k_gemm<128, 64, 16, 8, 8><<<grid, 128>>>(
            (const float*)p_h1, W2, (float*)p_h2, NN, DOUT, DHID);
    }
    // 8. attention layer 2
    k_logits2<<<(NN * 32) / 256, 256>>>(as2, ad2);
    k_exp2<<<(NE + 255) / 256, 256>>>(src, dst);
    k_invden2<<<(NN + 255) / 256, 256>>>();
    k_agg2<<<(NE * 16) / 256, 256>>>(src, dst);
    // 9. final LayerNorm -> d_out
    k_ln2<<<(NN * 32) / 256, 256>>>(b2, g2, be2, out);
}